// round 10
// baseline (speedup 1.0000x reference)
#include <cuda_runtime.h>
#include <math.h>

#define H    256
#define H2   512
#define SEQ  256
#define NL   4
#define VOC  50257
#define TPB  512
#define NWARP 16
#define CHB  16                          // chain blocks

#define GEMV_GRID 148
#define GEMV_TOTW (GEMV_GRID * NWARP)    // 2368
#define GEMV_ITERS 3                     // 3*2368*8 = 56832 >= VOC

// ---------------- scratch (device globals; no allocation allowed) ----------
__device__ __align__(16) float  g_attn_logits[SEQ];
__device__ __align__(16) float  g_gh[NL * 3 * H];    // h@whh.T + bhh
__device__ __align__(16) float  g_xbuf[2][H];
__device__ __align__(16) float2 g_red[GEMV_GRID];
__device__ __align__(16) unsigned g_cflag[CHB];      // monotonic chain flags
__device__ __align__(16) unsigned g_epoch[CHB];      // private launch counters

// ---------------- helpers ---------------------------------------------------
__device__ __forceinline__ float dot4f(float4 a, float4 b) {
    return fmaf(a.x, b.x, fmaf(a.y, b.y, fmaf(a.z, b.z, a.w * b.w)));
}
__device__ __forceinline__ float wredsum(float v) {
    #pragma unroll
    for (int o = 16; o; o >>= 1) v += __shfl_xor_sync(0xffffffffu, v, o);
    return v;
}
// packed 4-row warp reduce: lanes 0-7 hold full sum of d0, 8-15 d1, 16-23 d2,
// 24-31 d3.
__device__ __forceinline__ float red4(float d0, float d1, float d2, float d3, int lane) {
    bool h16 = (lane & 16) != 0, h8 = (lane & 8) != 0;
    float k0 = (h16 ? d2 : d0) + __shfl_xor_sync(0xffffffffu, h16 ? d0 : d2, 16);
    float k1 = (h16 ? d3 : d1) + __shfl_xor_sync(0xffffffffu, h16 ? d1 : d3, 16);
    float v  = (h8 ? k1 : k0) + __shfl_xor_sync(0xffffffffu, h8 ? k0 : k1, 8);
    v += __shfl_xor_sync(0xffffffffu, v, 4);
    v += __shfl_xor_sync(0xffffffffu, v, 2);
    v += __shfl_xor_sync(0xffffffffu, v, 1);
    return v;
}
// packed 8-row warp reduce: every lane ends with full sum of row (lane>>2);
// owner = (lane&3)==0.
__device__ __forceinline__ float red8(const float* d, int lane) {
    bool h16 = (lane & 16) != 0, h8 = (lane & 8) != 0, h4b = (lane & 4) != 0;
    float k0 = (h16 ? d[4] : d[0]) + __shfl_xor_sync(0xffffffffu, h16 ? d[0] : d[4], 16);
    float k1 = (h16 ? d[5] : d[1]) + __shfl_xor_sync(0xffffffffu, h16 ? d[1] : d[5], 16);
    float k2 = (h16 ? d[6] : d[2]) + __shfl_xor_sync(0xffffffffu, h16 ? d[2] : d[6], 16);
    float k3 = (h16 ? d[7] : d[3]) + __shfl_xor_sync(0xffffffffu, h16 ? d[3] : d[7], 16);
    float m0 = (h8 ? k2 : k0) + __shfl_xor_sync(0xffffffffu, h8 ? k0 : k2, 8);
    float m1 = (h8 ? k3 : k1) + __shfl_xor_sync(0xffffffffu, h8 ? k1 : k3, 8);
    float v  = (h4b ? m1 : m0) + __shfl_xor_sync(0xffffffffu, h4b ? m0 : m1, 4);
    v += __shfl_xor_sync(0xffffffffu, v, 2);
    v += __shfl_xor_sync(0xffffffffu, v, 1);
    return v;
}

// ====================== K1: attention logits + gh (grid 80) =================
__global__ void __launch_bounds__(TPB, 1)
k_logits_gh(const int* __restrict__ token,
            const float* __restrict__ hidden,
            const float* __restrict__ emb,
            const float* __restrict__ attn_w,
            const float* __restrict__ attn_b,
            const float* __restrict__ gru_whh,
            const float* __restrict__ gru_bhh)
{
    const int tid = threadIdx.x, bid = blockIdx.x;
    const int wid = tid >> 5, lane = tid & 31;
    __shared__ __align__(16) float s_in[H2];

    if (bid < 16) {
        const int tok = token[0];
        const float* erow = emb + (size_t)tok * H;
        s_in[tid] = (tid < H) ? __ldg(erow + tid) : __ldg(hidden + tid - H);
        __syncthreads();
        const float4* in4 = (const float4*)s_in;
        float4 xv[4];
        #pragma unroll
        for (int t = 0; t < 4; t++) xv[t] = in4[lane + 32 * t];
        const int r = bid * NWARP + wid;
        const float4* w4 = (const float4*)(attn_w + (size_t)r * H2);
        float4 A[4];
        #pragma unroll
        for (int t = 0; t < 4; t++) A[t] = __ldg(w4 + lane + 32 * t);
        float d = 0.f;
        #pragma unroll
        for (int t = 0; t < 4; t++) d += dot4f(A[t], xv[t]);
        d = wredsum(d);
        if (lane == 0) g_attn_logits[r] = d + __ldg(attn_b + r);
    } else {
        // gh = h @ whh.T + bhh : warp per (layer, j): 64 blocks x 16 = 1024
        int W = (bid - 16) * NWARP + wid;
        int l = W >> 8, j = W & 255;
        const float* whh = gru_whh + (size_t)l * 3 * H * H;
        const float4* h4 = (const float4*)(hidden + l * H);
        float4 ha = __ldg(h4 + lane), hb = __ldg(h4 + lane + 32);
        const float4* wr = (const float4*)(whh + (size_t)j * H);
        const float4* wz = (const float4*)(whh + (size_t)(H + j) * H);
        const float4* wn = (const float4*)(whh + (size_t)(2 * H + j) * H);
        float4 W0 = __ldg(wr + lane), W1 = __ldg(wr + lane + 32);
        float4 W2 = __ldg(wz + lane), W3 = __ldg(wz + lane + 32);
        float4 W4 = __ldg(wn + lane), W5 = __ldg(wn + lane + 32);
        float dr = dot4f(W0, ha) + dot4f(W1, hb);
        float dz = dot4f(W2, ha) + dot4f(W3, hb);
        float dn = dot4f(W4, ha) + dot4f(W5, hb);
        float v = red4(dr, dz, dn, 0.f, lane);
        int part = lane >> 3;
        if ((lane & 7) == 0 && part < 3)
            g_gh[(l * 3 + part) * H + j] = v + __ldg(gru_bhh + (l * 3 + part) * H + j);
    }
}

// ===== K2: chain — softmax + applied + comb + 4 GRU layers (grid 16) ========
__global__ void __launch_bounds__(TPB, 1)
k_chain(const int* __restrict__ token,
        const float* __restrict__ hidden,
        const float* __restrict__ enc,
        const float* __restrict__ emb,
        const float* __restrict__ comb_w,
        const float* __restrict__ comb_b,
        const float* __restrict__ gru_wih,
        const float* __restrict__ gru_bih,
        float* __restrict__ out)
{
    const int tid = threadIdx.x, bid = blockIdx.x;
    const int wid = tid >> 5, lane = tid & 31;
    __shared__ __align__(16) float s_in[H2];
    __shared__ __align__(16) float s_x[H];
    __shared__ __align__(16) float s_aw[SEQ];
    __shared__ __align__(16) float s_part[NWARP][H];
    __shared__ float s_red[NWARP];
    __shared__ float s_bc[2];
    __shared__ unsigned s_e;

    if (tid == 0) {
        unsigned e = g_epoch[bid];
        g_epoch[bid] = e + 1u;
        s_e = e;
    }
    __syncthreads();
    const unsigned cb = s_e * 4u;      // 4 flag increments per launch

    // ---- softmax over logits (redundant per block) ----
    float v = (tid < SEQ) ? g_attn_logits[tid] : -1e30f;
    float wm = v;
    #pragma unroll
    for (int o = 16; o; o >>= 1) wm = fmaxf(wm, __shfl_xor_sync(0xffffffffu, wm, o));
    if (lane == 0) s_red[wid] = wm;
    __syncthreads();
    if (tid == 0) {
        float m = s_red[0];
        #pragma unroll
        for (int w = 1; w < NWARP; w++) m = fmaxf(m, s_red[w]);
        s_bc[0] = m;
    }
    __syncthreads();
    float ex = (tid < SEQ) ? expf(v - s_bc[0]) : 0.f;
    float ws = ex;
    #pragma unroll
    for (int o = 16; o; o >>= 1) ws += __shfl_xor_sync(0xffffffffu, ws, o);
    if (lane == 0) s_red[wid] = ws;
    __syncthreads();
    if (tid == 0) {
        float s = 0.f;
        #pragma unroll
        for (int w = 0; w < NWARP; w++) s += s_red[w];
        s_bc[1] = s;
    }
    __syncthreads();
    float aw = ex / s_bc[1];
    if (tid < SEQ) {
        s_aw[tid] = aw;
        if (bid == 0) out[VOC + NL * H + tid] = aw;   // attn_weights output
    }
    __syncthreads();

    // ---- attn_applied (redundant per block): warp w covers seq [16w,16w+16)
    {
        float acc[8];
        #pragma unroll
        for (int c8 = 0; c8 < 8; c8++) acc[c8] = 0.f;
        int i0 = wid * 16;
        #pragma unroll 4
        for (int ii = 0; ii < 16; ii++) {
            float a = s_aw[i0 + ii];
            const float* er = enc + (size_t)(i0 + ii) * H;
            #pragma unroll
            for (int c8 = 0; c8 < 8; c8++)
                acc[c8] = fmaf(a, __ldg(er + c8 * 32 + lane), acc[c8]);
        }
        #pragma unroll
        for (int c8 = 0; c8 < 8; c8++) s_part[wid][c8 * 32 + lane] = acc[c8];
    }
    __syncthreads();
    {
        const int tok = token[0];
        const float* erow = emb + (size_t)tok * H;
        if (tid < H) {
            float ap = 0.f;
            #pragma unroll
            for (int w = 0; w < NWARP; w++) ap += s_part[w][tid];
            s_in[H + tid] = ap;
            s_in[tid] = __ldg(erow + tid);
        }
    }
    __syncthreads();

    // ---- comb: warp per row j (16 blocks x 16 warps = 256) ----
    const int j = bid * NWARP + wid;
    {
        const float4* in4 = (const float4*)s_in;
        float4 xv[4];
        #pragma unroll
        for (int t = 0; t < 4; t++) xv[t] = in4[lane + 32 * t];
        const float4* w4 = (const float4*)(comb_w + (size_t)j * H2);
        float4 A[4];
        #pragma unroll
        for (int t = 0; t < 4; t++) A[t] = __ldg(w4 + lane + 32 * t);
        float d = 0.f;
        #pragma unroll
        for (int t = 0; t < 4; t++) d += dot4f(A[t], xv[t]);
        d = wredsum(d);
        if (lane == 0)
            __stcg(&g_xbuf[0][j], fmaxf(d + __ldg(comb_b + j), 0.f));
    }

    // ---- preload GRU layer-0 weights + epilogue scalars (indep. of x) ------
    float4 Wc[6];
    float c_ghr, c_ghz, c_ghn, c_br, c_bz, c_bn, c_h;
    {
        const float* wih = gru_wih;
        const float4* wr = (const float4*)(wih + (size_t)j * H);
        const float4* wz = (const float4*)(wih + (size_t)(H + j) * H);
        const float4* wn = (const float4*)(wih + (size_t)(2 * H + j) * H);
        Wc[0] = __ldg(wr + lane); Wc[1] = __ldg(wr + lane + 32);
        Wc[2] = __ldg(wz + lane); Wc[3] = __ldg(wz + lane + 32);
        Wc[4] = __ldg(wn + lane); Wc[5] = __ldg(wn + lane + 32);
        c_ghr = g_gh[0 * H + j]; c_ghz = g_gh[1 * H + j]; c_ghn = g_gh[2 * H + j];
        c_br = __ldg(gru_bih + 0 * H + j);
        c_bz = __ldg(gru_bih + 1 * H + j);
        c_bn = __ldg(gru_bih + 2 * H + j);
        c_h  = __ldg(hidden + j);
    }

    // ---- GRU layers with pipelined weight loads ----------------------------
    #pragma unroll
    for (int l = 0; l < NL; l++) {
        // 16-block barrier: x(l) stores visible
        __syncthreads();
        if (tid == 0) { __threadfence(); *(volatile unsigned*)&g_cflag[bid] = cb + 1 + l; }
        if (tid < CHB) {
            while (*(volatile unsigned*)&g_cflag[tid] < cb + 1 + l) { }
        }
        __syncthreads();

        if (tid < H) s_x[tid] = __ldcg(&g_xbuf[l & 1][tid]);
        __syncthreads();

        // prefetch next layer's weights + scalars (independent of this layer)
        float4 Wn[6];
        float n_ghr = 0.f, n_ghz = 0.f, n_ghn = 0.f, n_br = 0.f, n_bz = 0.f,
              n_bn = 0.f, n_h = 0.f;
        if (l + 1 < NL) {
            const float* wih = gru_wih + (size_t)(l + 1) * 3 * H * H;
            const float4* wr = (const float4*)(wih + (size_t)j * H);
            const float4* wz = (const float4*)(wih + (size_t)(H + j) * H);
            const float4* wn = (const float4*)(wih + (size_t)(2 * H + j) * H);
            Wn[0] = __ldg(wr + lane); Wn[1] = __ldg(wr + lane + 32);
            Wn[2] = __ldg(wz + lane); Wn[3] = __ldg(wz + lane + 32);
            Wn[4] = __ldg(wn + lane); Wn[5] = __ldg(wn + lane + 32);
            n_ghr = g_gh[((l + 1) * 3 + 0) * H + j];
            n_ghz = g_gh[((l + 1) * 3 + 1) * H + j];
            n_ghn = g_gh[((l + 1) * 3 + 2) * H + j];
            n_br = __ldg(gru_bih + ((l + 1) * 3 + 0) * H + j);
            n_bz = __ldg(gru_bih + ((l + 1) * 3 + 1) * H + j);
            n_bn = __ldg(gru_bih + ((l + 1) * 3 + 2) * H + j);
            n_h  = __ldg(hidden + (l + 1) * H + j);
        }

        const float4* x4 = (const float4*)s_x;
        float4 xa = x4[lane], xb = x4[lane + 32];
        float dr = dot4f(Wc[0], xa) + dot4f(Wc[1], xb);
        float dz = dot4f(Wc[2], xa) + dot4f(Wc[3], xb);
        float dn = dot4f(Wc[4], xa) + dot4f(Wc[5], xb);
        float vv = red4(dr, dz, dn, 0.f, lane);
        float rs = __shfl_sync(0xffffffffu, vv, 0);
        float zs = __shfl_sync(0xffffffffu, vv, 8);
        float ns = __shfl_sync(0xffffffffu, vv, 16);
        if (lane == 0) {
            float r = 1.f / (1.f + expf(-((rs + c_br) + c_ghr)));
            float z = 1.f / (1.f + expf(-((zs + c_bz) + c_ghz)));
            float n = tanhf((ns + c_bn) + r * c_ghn);
            float hnew = (1.f - z) * n + z * c_h;
            __stcg(&g_xbuf[(l + 1) & 1][j], hnew);
            out[VOC + l * H + j] = hnew;      // hidden_new output
        }
        #pragma unroll
        for (int q = 0; q < 6; q++) Wc[q] = Wn[q];
        c_ghr = n_ghr; c_ghz = n_ghz; c_ghn = n_ghn;
        c_br = n_br; c_bz = n_bz; c_bn = n_bn; c_h = n_h;
    }
}

// ====================== K3: GEMV + per-block (m,s) (grid 148) ===============
__global__ void __launch_bounds__(TPB, 1)
k_gemv(const float* __restrict__ out_w,
       const float* __restrict__ out_b,
       float* __restrict__ out)
{
    const int tid = threadIdx.x, bid = blockIdx.x;
    const int wid = tid >> 5, lane = tid & 31;
    __shared__ __align__(16) float s_x[H];
    __shared__ float s_ms[2 * NWARP];

    if (tid < H) s_x[tid] = g_xbuf[0][tid];   // NL even -> buf 0
    __syncthreads();
    const float4* x4 = (const float4*)s_x;
    float4 xa = x4[lane], xb = x4[lane + 32];
    const int gwid = bid * NWARP + wid;
    const int rown = lane >> 2;
    const bool own = (lane & 3) == 0;
    float mM = -1e30f, sS = 0.f;
    #pragma unroll 1
    for (int it = 0; it < GEMV_ITERS; it++) {
        int r0 = (it * GEMV_TOTW + gwid) * 8;
        int myrow = r0 + rown;
        float bias = (own && myrow < VOC) ? __ldg(out_b + myrow) : 0.f;
        float d[8];
        #pragma unroll
        for (int i = 0; i < 8; i++) {
            int row = r0 + i;
            float s = 0.f;
            if (row < VOC) {
                const float4* wr = (const float4*)(out_w + (size_t)row * H);
                float4 a0 = __ldg(wr + lane), a1 = __ldg(wr + lane + 32);
                s = dot4f(a0, xa) + dot4f(a1, xb);
            }
            d[i] = s;
        }
        float v = red8(d, lane);
        if (own && myrow < VOC) {
            v += bias;
            out[myrow] = v;
            float m2 = fmaxf(mM, v);
            sS = sS * expf(mM - m2) + expf(v - m2);
            mM = m2;
        }
    }
    #pragma unroll
    for (int o = 16; o; o >>= 1) {
        float om = __shfl_xor_sync(0xffffffffu, mM, o);
        float os = __shfl_xor_sync(0xffffffffu, sS, o);
        float m2 = fmaxf(mM, om);
        sS = sS * expf(mM - m2) + os * expf(om - m2);
        mM = m2;
    }
    if (lane == 0) { s_ms[wid] = mM; s_ms[NWARP + wid] = sS; }
    __syncthreads();
    if (tid == 0) {
        float M = s_ms[0], S = s_ms[NWARP];
        #pragma unroll
        for (int w = 1; w < NWARP; w++) {
            float m2 = fmaxf(M, s_ms[w]);
            S = S * expf(M - m2) + s_ms[NWARP + w] * expf(s_ms[w] - m2);
            M = m2;
        }
        g_red[bid] = make_float2(M, S);
    }
}

// ====================== K4: finalize lse + subtract (grid 148) ==============
__global__ void __launch_bounds__(TPB, 1)
k_final(float* __restrict__ out)
{
    const int tid = threadIdx.x, bid = blockIdx.x;
    const int wid = tid >> 5, lane = tid & 31;
    __shared__ float s_lse;

    if (wid == 0) {
        float M = -1e30f, S = 0.f;
        for (int k = lane; k < GEMV_GRID; k += 32) {
            float2 p = g_red[k];
            float m2 = fmaxf(M, p.x);
            S = S * expf(M - m2) + p.y * expf(p.x - m2);
            M = m2;
        }
        #pragma unroll
        for (int o = 16; o; o >>= 1) {
            float om = __shfl_xor_sync(0xffffffffu, M, o);
            float os = __shfl_xor_sync(0xffffffffu, S, o);
            float m2 = fmaxf(M, om);
            S = S * expf(M - m2) + os * expf(om - m2);
            M = m2;
        }
        if (lane == 0) s_lse = M + logf(S);
    }
    __syncthreads();
    float lse = s_lse;
    int i = bid * TPB + tid;          // 148*512 = 75776 >= VOC, one pass
    if (i < VOC) out[i] -= lse;
}

extern "C" void kernel_launch(void* const* d_in, const int* in_sizes, int n_in,
                              void* d_out, int out_size) {
    const int*   token   = (const int*)d_in[0];
    const float* hidden  = (const float*)d_in[1];
    const float* enc     = (const float*)d_in[2];
    const float* emb     = (const float*)d_in[3];
    const float* attn_w  = (const float*)d_in[4];
    const float* attn_b  = (const float*)d_in[5];
    const float* comb_w  = (const float*)d_in[6];
    const float* comb_b  = (const float*)d_in[7];
    const float* gru_wih = (const float*)d_in[8];
    const float* gru_whh = (const float*)d_in[9];
    const float* gru_bih = (const float*)d_in[10];
    const float* gru_bhh = (const float*)d_in[11];
    const float* out_w   = (const float*)d_in[12];
    const float* out_b   = (const float*)d_in[13];
    float* out = (float*)d_out;

    k_logits_gh<<<80, TPB>>>(token, hidden, emb, attn_w, attn_b, gru_whh, gru_bhh);
    k_chain<<<CHB, TPB>>>(token, hidden, enc, emb, comb_w, comb_b,
                          gru_wih, gru_bih, out);
    k_gemv<<<GEMV_GRID, TPB>>>(out_w, out_b, out);
    k_final<<<GEMV_GRID, TPB>>>(out);
}

// round 11
// speedup vs baseline: 1.0114x; 1.0114x over previous
#include <cuda_runtime.h>
#include <math.h>

#define H    256
#define H2   512
#define SEQ  256
#define NL   4
#define VOC  50257
#define TPB  512
#define NWARP 16

#define TPB_G 256
#define GEMV_GRID 296
#define GEMV_TOTW (GEMV_GRID * 8)       // 2368 warps
#define GEMV_ITERS 3                    // 3*2368*8 = 56832 >= VOC

// ---------------- scratch (device globals; no allocation allowed) ----------
__device__ __align__(16) float  g_attn_logits[SEQ];
__device__ __align__(16) float  g_gh[NL * 3 * H];    // h@whh.T + bhh
__device__ __align__(16) float  g_xbuf[2][H];
__device__ __align__(16) float2 g_red[GEMV_GRID];

// ---------------- helpers ---------------------------------------------------
__device__ __forceinline__ float dot4f(float4 a, float4 b) {
    return fmaf(a.x, b.x, fmaf(a.y, b.y, fmaf(a.z, b.z, a.w * b.w)));
}
__device__ __forceinline__ float wredsum(float v) {
    #pragma unroll
    for (int o = 16; o; o >>= 1) v += __shfl_xor_sync(0xffffffffu, v, o);
    return v;
}
// packed 4-row warp reduce: lanes 0-7 hold full sum of d0, 8-15 d1, 16-23 d2,
// 24-31 d3.
__device__ __forceinline__ float red4(float d0, float d1, float d2, float d3, int lane) {
    bool h16 = (lane & 16) != 0, h8 = (lane & 8) != 0;
    float k0 = (h16 ? d2 : d0) + __shfl_xor_sync(0xffffffffu, h16 ? d0 : d2, 16);
    float k1 = (h16 ? d3 : d1) + __shfl_xor_sync(0xffffffffu, h16 ? d1 : d3, 16);
    float v  = (h8 ? k1 : k0) + __shfl_xor_sync(0xffffffffu, h8 ? k0 : k1, 8);
    v += __shfl_xor_sync(0xffffffffu, v, 4);
    v += __shfl_xor_sync(0xffffffffu, v, 2);
    v += __shfl_xor_sync(0xffffffffu, v, 1);
    return v;
}
// packed 8-row warp reduce: every lane ends with full sum of row (lane>>2);
// owner = (lane&3)==0.
__device__ __forceinline__ float red8(const float* d, int lane) {
    bool h16 = (lane & 16) != 0, h8 = (lane & 8) != 0, h4b = (lane & 4) != 0;
    float k0 = (h16 ? d[4] : d[0]) + __shfl_xor_sync(0xffffffffu, h16 ? d[0] : d[4], 16);
    float k1 = (h16 ? d[5] : d[1]) + __shfl_xor_sync(0xffffffffu, h16 ? d[1] : d[5], 16);
    float k2 = (h16 ? d[6] : d[2]) + __shfl_xor_sync(0xffffffffu, h16 ? d[2] : d[6], 16);
    float k3 = (h16 ? d[7] : d[3]) + __shfl_xor_sync(0xffffffffu, h16 ? d[3] : d[7], 16);
    float m0 = (h8 ? k2 : k0) + __shfl_xor_sync(0xffffffffu, h8 ? k0 : k2, 8);
    float m1 = (h8 ? k3 : k1) + __shfl_xor_sync(0xffffffffu, h8 ? k1 : k3, 8);
    float v  = (h4b ? m1 : m0) + __shfl_xor_sync(0xffffffffu, h4b ? m0 : m1, 4);
    v += __shfl_xor_sync(0xffffffffu, v, 2);
    v += __shfl_xor_sync(0xffffffffu, v, 1);
    return v;
}

// ====================== K1: attention logits + gh (grid 80) =================
__global__ void __launch_bounds__(TPB, 1)
k_logits_gh(const int* __restrict__ token,
            const float* __restrict__ hidden,
            const float* __restrict__ emb,
            const float* __restrict__ attn_w,
            const float* __restrict__ attn_b,
            const float* __restrict__ gru_whh,
            const float* __restrict__ gru_bhh)
{
    const int tid = threadIdx.x, bid = blockIdx.x;
    const int wid = tid >> 5, lane = tid & 31;
    __shared__ __align__(16) float s_in[H2];

    if (bid < 16) {
        const int tok = token[0];
        const float* erow = emb + (size_t)tok * H;
        s_in[tid] = (tid < H) ? __ldg(erow + tid) : __ldg(hidden + tid - H);
        __syncthreads();
        const float4* in4 = (const float4*)s_in;
        float4 xv[4];
        #pragma unroll
        for (int t = 0; t < 4; t++) xv[t] = in4[lane + 32 * t];
        const int r = bid * NWARP + wid;
        const float4* w4 = (const float4*)(attn_w + (size_t)r * H2);
        float4 A[4];
        #pragma unroll
        for (int t = 0; t < 4; t++) A[t] = __ldg(w4 + lane + 32 * t);
        float d = 0.f;
        #pragma unroll
        for (int t = 0; t < 4; t++) d += dot4f(A[t], xv[t]);
        d = wredsum(d);
        if (lane == 0) g_attn_logits[r] = d + __ldg(attn_b + r);
    } else {
        // gh = h @ whh.T + bhh : warp per (layer, j): 64 blocks x 16 = 1024
        int W = (bid - 16) * NWARP + wid;
        int l = W >> 8, j = W & 255;
        const float* whh = gru_whh + (size_t)l * 3 * H * H;
        const float4* h4 = (const float4*)(hidden + l * H);
        float4 ha = __ldg(h4 + lane), hb = __ldg(h4 + lane + 32);
        const float4* wr = (const float4*)(whh + (size_t)j * H);
        const float4* wz = (const float4*)(whh + (size_t)(H + j) * H);
        const float4* wn = (const float4*)(whh + (size_t)(2 * H + j) * H);
        float4 W0 = __ldg(wr + lane), W1 = __ldg(wr + lane + 32);
        float4 W2 = __ldg(wz + lane), W3 = __ldg(wz + lane + 32);
        float4 W4 = __ldg(wn + lane), W5 = __ldg(wn + lane + 32);
        float dr = dot4f(W0, ha) + dot4f(W1, hb);
        float dz = dot4f(W2, ha) + dot4f(W3, hb);
        float dn = dot4f(W4, ha) + dot4f(W5, hb);
        float v = red4(dr, dz, dn, 0.f, lane);
        int part = lane >> 3;
        if ((lane & 7) == 0 && part < 3)
            g_gh[(l * 3 + part) * H + j] = v + __ldg(gru_bhh + (l * 3 + part) * H + j);
    }
}

// ====== K2: softmax + attn_applied + comb (grid 16) ========================
__global__ void __launch_bounds__(TPB, 1)
k_attn_comb(const int* __restrict__ token,
            const float* __restrict__ enc,
            const float* __restrict__ emb,
            const float* __restrict__ comb_w,
            const float* __restrict__ comb_b,
            float* __restrict__ out)
{
    const int tid = threadIdx.x, bid = blockIdx.x;
    const int wid = tid >> 5, lane = tid & 31;
    __shared__ __align__(16) float s_in[H2];
    __shared__ __align__(16) float s_aw[SEQ];
    __shared__ __align__(16) float s_part[NWARP][H];
    __shared__ float s_red[NWARP];
    __shared__ float s_bc[2];

    // ---- softmax over logits (redundant per block) ----
    float v = (tid < SEQ) ? g_attn_logits[tid] : -1e30f;
    float wm = v;
    #pragma unroll
    for (int o = 16; o; o >>= 1) wm = fmaxf(wm, __shfl_xor_sync(0xffffffffu, wm, o));
    if (lane == 0) s_red[wid] = wm;
    __syncthreads();
    if (tid == 0) {
        float m = s_red[0];
        #pragma unroll
        for (int w = 1; w < NWARP; w++) m = fmaxf(m, s_red[w]);
        s_bc[0] = m;
    }
    __syncthreads();
    float ex = (tid < SEQ) ? expf(v - s_bc[0]) : 0.f;
    float ws = ex;
    #pragma unroll
    for (int o = 16; o; o >>= 1) ws += __shfl_xor_sync(0xffffffffu, ws, o);
    if (lane == 0) s_red[wid] = ws;
    __syncthreads();
    if (tid == 0) {
        float s = 0.f;
        #pragma unroll
        for (int w = 0; w < NWARP; w++) s += s_red[w];
        s_bc[1] = s;
    }
    __syncthreads();
    float aw = ex / s_bc[1];
    if (tid < SEQ) {
        s_aw[tid] = aw;
        if (bid == 0) out[VOC + NL * H + tid] = aw;   // attn_weights output
    }
    __syncthreads();

    // ---- attn_applied: warp w covers seq [16w,16w+16), lanes cover columns
    {
        float acc[8];
        #pragma unroll
        for (int c8 = 0; c8 < 8; c8++) acc[c8] = 0.f;
        int i0 = wid * 16;
        #pragma unroll 4
        for (int ii = 0; ii < 16; ii++) {
            float a = s_aw[i0 + ii];
            const float* er = enc + (size_t)(i0 + ii) * H;
            #pragma unroll
            for (int c8 = 0; c8 < 8; c8++)
                acc[c8] = fmaf(a, __ldg(er + c8 * 32 + lane), acc[c8]);
        }
        #pragma unroll
        for (int c8 = 0; c8 < 8; c8++) s_part[wid][c8 * 32 + lane] = acc[c8];
    }
    __syncthreads();
    {
        const int tok = token[0];
        const float* erow = emb + (size_t)tok * H;
        if (tid < H) {
            float ap = 0.f;
            #pragma unroll
            for (int w = 0; w < NWARP; w++) ap += s_part[w][tid];
            s_in[H + tid] = ap;
            s_in[tid] = __ldg(erow + tid);
        }
    }
    __syncthreads();

    // ---- comb: warp per row j (16 blocks x 16 warps = 256) ----
    {
        const float4* in4 = (const float4*)s_in;
        float4 xv[4];
        #pragma unroll
        for (int t = 0; t < 4; t++) xv[t] = in4[lane + 32 * t];
        const int j = bid * NWARP + wid;
        const float4* w4 = (const float4*)(comb_w + (size_t)j * H2);
        float4 A[4];
        #pragma unroll
        for (int t = 0; t < 4; t++) A[t] = __ldg(w4 + lane + 32 * t);
        float d = 0.f;
        #pragma unroll
        for (int t = 0; t < 4; t++) d += dot4f(A[t], xv[t]);
        d = wredsum(d);
        if (lane == 0)
            g_xbuf[0][j] = fmaxf(d + __ldg(comb_b + j), 0.f);
    }
}

// ====================== K3: one GRU layer (grid 16) =========================
__global__ void __launch_bounds__(TPB, 1)
k_gru(const float* __restrict__ hidden,
      const float* __restrict__ gru_wih,
      const float* __restrict__ gru_bih,
      float* __restrict__ out, int l)
{
    const int tid = threadIdx.x, bid = blockIdx.x;
    const int wid = tid >> 5, lane = tid & 31;
    __shared__ __align__(16) float s_x[H];

    if (tid < H) s_x[tid] = g_xbuf[l & 1][tid];
    __syncthreads();
    const int j = bid * NWARP + wid;
    const float* wih = gru_wih + (size_t)l * 3 * H * H;
    float p_ghr = g_gh[(l * 3 + 0) * H + j];
    float p_ghz = g_gh[(l * 3 + 1) * H + j];
    float p_ghn = g_gh[(l * 3 + 2) * H + j];
    float p_br  = __ldg(gru_bih + (l * 3 + 0) * H + j);
    float p_bz  = __ldg(gru_bih + (l * 3 + 1) * H + j);
    float p_bn  = __ldg(gru_bih + (l * 3 + 2) * H + j);
    float p_h   = __ldg(hidden + l * H + j);
    const float4* x4 = (const float4*)s_x;
    float4 xa = x4[lane], xb = x4[lane + 32];
    const float4* wr = (const float4*)(wih + (size_t)j * H);
    const float4* wz = (const float4*)(wih + (size_t)(H + j) * H);
    const float4* wn = (const float4*)(wih + (size_t)(2 * H + j) * H);
    float4 W0 = __ldg(wr + lane), W1 = __ldg(wr + lane + 32);
    float4 W2 = __ldg(wz + lane), W3 = __ldg(wz + lane + 32);
    float4 W4 = __ldg(wn + lane), W5 = __ldg(wn + lane + 32);
    float dr = dot4f(W0, xa) + dot4f(W1, xb);
    float dz = dot4f(W2, xa) + dot4f(W3, xb);
    float dn = dot4f(W4, xa) + dot4f(W5, xb);
    float v = red4(dr, dz, dn, 0.f, lane);
    float rs = __shfl_sync(0xffffffffu, v, 0);
    float zs = __shfl_sync(0xffffffffu, v, 8);
    float ns = __shfl_sync(0xffffffffu, v, 16);
    if (lane == 0) {
        float r = 1.f / (1.f + expf(-((rs + p_br) + p_ghr)));
        float z = 1.f / (1.f + expf(-((zs + p_bz) + p_ghz)));
        float n = tanhf((ns + p_bn) + r * p_ghn);
        float hnew = (1.f - z) * n + z * p_h;
        g_xbuf[(l + 1) & 1][j] = hnew;
        out[VOC + l * H + j] = hnew;      // hidden_new output
    }
}

// ====== K4: GEMV, 2 CTAs/SM, front-batched loads (grid 296 x 256) ===========
__global__ void __launch_bounds__(TPB_G, 2)
k_gemv(const float* __restrict__ out_w,
       const float* __restrict__ out_b,
       float* __restrict__ out)
{
    const int tid = threadIdx.x, bid = blockIdx.x;
    const int wid = tid >> 5, lane = tid & 31;
    __shared__ __align__(16) float s_x[H];
    __shared__ float s_ms[16];

    if (tid < H) s_x[tid] = g_xbuf[0][tid];   // NL even -> buf 0
    __syncthreads();
    const float4* x4 = (const float4*)s_x;
    float4 xa = x4[lane], xb = x4[lane + 32];
    const int gwid = bid * 8 + wid;
    const int rown = lane >> 2;
    const bool own = (lane & 3) == 0;
    float mM = -1e30f, sS = 0.f;
    #pragma unroll 1
    for (int it = 0; it < GEMV_ITERS; it++) {
        int r0 = (it * GEMV_TOTW + gwid) * 8;
        int myrow = r0 + rown;
        // front-batched, branch-free loads (clamped rows stay in range)
        float4 A[16];
        #pragma unroll
        for (int i = 0; i < 8; i++) {
            int row = r0 + i; if (row > VOC - 1) row = VOC - 1;
            const float4* wr = (const float4*)(out_w + (size_t)row * H);
            A[2 * i]     = __ldg(wr + lane);
            A[2 * i + 1] = __ldg(wr + lane + 32);
        }
        float bias = (own && myrow < VOC) ? __ldg(out_b + myrow) : 0.f;
        float d[8];
        #pragma unroll
        for (int i = 0; i < 8; i++)
            d[i] = dot4f(A[2 * i], xa) + dot4f(A[2 * i + 1], xb);
        float v = red8(d, lane);
        if (own && myrow < VOC) {
            v += bias;
            out[myrow] = v;
            float m2 = fmaxf(mM, v);
            sS = sS * expf(mM - m2) + expf(v - m2);
            mM = m2;
        }
    }
    #pragma unroll
    for (int o = 16; o; o >>= 1) {
        float om = __shfl_xor_sync(0xffffffffu, mM, o);
        float os = __shfl_xor_sync(0xffffffffu, sS, o);
        float m2 = fmaxf(mM, om);
        sS = sS * expf(mM - m2) + os * expf(om - m2);
        mM = m2;
    }
    if (lane == 0) { s_ms[wid] = mM; s_ms[8 + wid] = sS; }
    __syncthreads();
    if (tid == 0) {
        float M = s_ms[0], S = s_ms[8];
        #pragma unroll
        for (int w = 1; w < 8; w++) {
            float m2 = fmaxf(M, s_ms[w]);
            S = S * expf(M - m2) + s_ms[8 + w] * expf(s_ms[w] - m2);
            M = m2;
        }
        g_red[bid] = make_float2(M, S);
    }
}

// ====================== K5: finalize lse + subtract (grid 296) ==============
__global__ void __launch_bounds__(TPB_G, 2)
k_final(float* __restrict__ out)
{
    const int tid = threadIdx.x, bid = blockIdx.x;
    const int wid = tid >> 5, lane = tid & 31;
    __shared__ float s_lse;

    if (wid == 0) {
        float M = -1e30f, S = 0.f;
        for (int k = lane; k < GEMV_GRID; k += 32) {
            float2 p = g_red[k];
            float m2 = fmaxf(M, p.x);
            S = S * expf(M - m2) + p.y * expf(p.x - m2);
            M = m2;
        }
        #pragma unroll
        for (int o = 16; o; o >>= 1) {
            float om = __shfl_xor_sync(0xffffffffu, M, o);
            float os = __shfl_xor_sync(0xffffffffu, S, o);
            float m2 = fmaxf(M, om);
            S = S * expf(M - m2) + os * expf(om - m2);
            M = m2;
        }
        if (lane == 0) s_lse = M + logf(S);
    }
    __syncthreads();
    float lse = s_lse;
    int i = bid * TPB_G + tid;        // 296*256 = 75776 >= VOC, one pass
    if (i < VOC) out[i] -= lse;
}

extern "C" void kernel_launch(void* const* d_in, const int* in_sizes, int n_in,
                              void* d_out, int out_size) {
    const int*   token   = (const int*)d_in[0];
    const float* hidden  = (const float*)d_in[1];
    const float* enc     = (const float*)d_in[2];
    const float* emb     = (const float*)d_in[3];
    const float* attn_w  = (const float*)d_in[4];
    const float* attn_b  = (const float*)d_in[5];
    const float* comb_w  = (const float*)d_in[6];
    const float* comb_b  = (const float*)d_in[7];
    const float* gru_wih = (const float*)d_in[8];
    const float* gru_whh = (const float*)d_in[9];
    const float* gru_bih = (const float*)d_in[10];
    const float* gru_bhh = (const float*)d_in[11];
    const float* out_w   = (const float*)d_in[12];
    const float* out_b   = (const float*)d_in[13];
    float* out = (float*)d_out;

    k_logits_gh<<<80, TPB>>>(token, hidden, emb, attn_w, attn_b, gru_whh, gru_bhh);
    k_attn_comb<<<16, TPB>>>(token, enc, emb, comb_w, comb_b, out);
    for (int l = 0; l < NL; l++)
        k_gru<<<16, TPB>>>(hidden, gru_wih, gru_bih, out, l);
    k_gemv<<<GEMV_GRID, TPB_G>>>(out_w, out_b, out);
    k_final<<<GEMV_GRID, TPB_G>>>(out);
}

// round 12
// speedup vs baseline: 1.1527x; 1.1396x over previous
#include <cuda_runtime.h>
#include <math.h>

#define H    256
#define H2   512
#define SEQ  256
#define NL   4
#define VOC  50257
#define TPB  512
#define NWARP 16

#define GEMV_GRID 148
#define GEMV_TOTW (GEMV_GRID * NWARP)   // 2368
#define GEMV_ITERS 3                    // 3*2368*8 = 56832 >= VOC

// ---------------- scratch (device globals; no allocation allowed) ----------
__device__ __align__(16) float  g_attn_logits[SEQ];
__device__ __align__(16) float  g_gh[NL * 3 * H];    // h@whh.T + bhh
__device__ __align__(16) float  g_xbuf[2][H];
__device__ __align__(16) float2 g_red[GEMV_GRID];

// ---------------- PDL helpers -----------------------------------------------
__device__ __forceinline__ void pdl_wait() {
    asm volatile("griddepcontrol.wait;" ::: "memory");
}
__device__ __forceinline__ void pdl_trigger() {
    asm volatile("griddepcontrol.launch_dependents;" ::: "memory");
}

// ---------------- math helpers ----------------------------------------------
__device__ __forceinline__ float dot4f(float4 a, float4 b) {
    return fmaf(a.x, b.x, fmaf(a.y, b.y, fmaf(a.z, b.z, a.w * b.w)));
}
__device__ __forceinline__ float wredsum(float v) {
    #pragma unroll
    for (int o = 16; o; o >>= 1) v += __shfl_xor_sync(0xffffffffu, v, o);
    return v;
}
// packed 4-row warp reduce: lanes 0-7 hold full sum of d0, 8-15 d1, 16-23 d2,
// 24-31 d3.
__device__ __forceinline__ float red4(float d0, float d1, float d2, float d3, int lane) {
    bool h16 = (lane & 16) != 0, h8 = (lane & 8) != 0;
    float k0 = (h16 ? d2 : d0) + __shfl_xor_sync(0xffffffffu, h16 ? d0 : d2, 16);
    float k1 = (h16 ? d3 : d1) + __shfl_xor_sync(0xffffffffu, h16 ? d1 : d3, 16);
    float v  = (h8 ? k1 : k0) + __shfl_xor_sync(0xffffffffu, h8 ? k0 : k1, 8);
    v += __shfl_xor_sync(0xffffffffu, v, 4);
    v += __shfl_xor_sync(0xffffffffu, v, 2);
    v += __shfl_xor_sync(0xffffffffu, v, 1);
    return v;
}
// packed 8-row warp reduce: every lane ends with full sum of row (lane>>2);
// owner = (lane&3)==0.
__device__ __forceinline__ float red8(const float* d, int lane) {
    bool h16 = (lane & 16) != 0, h8 = (lane & 8) != 0, h4b = (lane & 4) != 0;
    float k0 = (h16 ? d[4] : d[0]) + __shfl_xor_sync(0xffffffffu, h16 ? d[0] : d[4], 16);
    float k1 = (h16 ? d[5] : d[1]) + __shfl_xor_sync(0xffffffffu, h16 ? d[1] : d[5], 16);
    float k2 = (h16 ? d[6] : d[2]) + __shfl_xor_sync(0xffffffffu, h16 ? d[2] : d[6], 16);
    float k3 = (h16 ? d[7] : d[3]) + __shfl_xor_sync(0xffffffffu, h16 ? d[3] : d[7], 16);
    float m0 = (h8 ? k2 : k0) + __shfl_xor_sync(0xffffffffu, h8 ? k0 : k2, 8);
    float m1 = (h8 ? k3 : k1) + __shfl_xor_sync(0xffffffffu, h8 ? k1 : k3, 8);
    float v  = (h4b ? m1 : m0) + __shfl_xor_sync(0xffffffffu, h4b ? m0 : m1, 4);
    v += __shfl_xor_sync(0xffffffffu, v, 2);
    v += __shfl_xor_sync(0xffffffffu, v, 1);
    return v;
}

// ====================== K1: attention logits + gh (grid 80) =================
__global__ void __launch_bounds__(TPB, 1)
k_logits_gh(const int* __restrict__ token,
            const float* __restrict__ hidden,
            const float* __restrict__ emb,
            const float* __restrict__ attn_w,
            const float* __restrict__ attn_b,
            const float* __restrict__ gru_whh,
            const float* __restrict__ gru_bhh)
{
    const int tid = threadIdx.x, bid = blockIdx.x;
    const int wid = tid >> 5, lane = tid & 31;
    __shared__ __align__(16) float s_in[H2];

    if (bid < 16) {
        const int tok = token[0];
        const float* erow = emb + (size_t)tok * H;
        s_in[tid] = (tid < H) ? __ldg(erow + tid) : __ldg(hidden + tid - H);
        __syncthreads();
        const float4* in4 = (const float4*)s_in;
        float4 xv[4];
        #pragma unroll
        for (int t = 0; t < 4; t++) xv[t] = in4[lane + 32 * t];
        const int r = bid * NWARP + wid;
        const float4* w4 = (const float4*)(attn_w + (size_t)r * H2);
        float4 A[4];
        #pragma unroll
        for (int t = 0; t < 4; t++) A[t] = __ldg(w4 + lane + 32 * t);
        float d = 0.f;
        #pragma unroll
        for (int t = 0; t < 4; t++) d += dot4f(A[t], xv[t]);
        d = wredsum(d);
        if (lane == 0) g_attn_logits[r] = d + __ldg(attn_b + r);
    } else {
        // gh = h @ whh.T + bhh : warp per (layer, j): 64 blocks x 16 = 1024
        int W = (bid - 16) * NWARP + wid;
        int l = W >> 8, j = W & 255;
        const float* whh = gru_whh + (size_t)l * 3 * H * H;
        const float4* h4 = (const float4*)(hidden + l * H);
        float4 ha = __ldg(h4 + lane), hb = __ldg(h4 + lane + 32);
        const float4* wr = (const float4*)(whh + (size_t)j * H);
        const float4* wz = (const float4*)(whh + (size_t)(H + j) * H);
        const float4* wn = (const float4*)(whh + (size_t)(2 * H + j) * H);
        float4 W0 = __ldg(wr + lane), W1 = __ldg(wr + lane + 32);
        float4 W2 = __ldg(wz + lane), W3 = __ldg(wz + lane + 32);
        float4 W4 = __ldg(wn + lane), W5 = __ldg(wn + lane + 32);
        float dr = dot4f(W0, ha) + dot4f(W1, hb);
        float dz = dot4f(W2, ha) + dot4f(W3, hb);
        float dn = dot4f(W4, ha) + dot4f(W5, hb);
        float v = red4(dr, dz, dn, 0.f, lane);
        int part = lane >> 3;
        if ((lane & 7) == 0 && part < 3)
            g_gh[(l * 3 + part) * H + j] = v + __ldg(gru_bhh + (l * 3 + part) * H + j);
    }
    __threadfence();
    pdl_trigger();
}

// ====== K2: softmax + attn_applied + comb (grid 16) ========================
__global__ void __launch_bounds__(TPB, 1)
k_attn_comb(const int* __restrict__ token,
            const float* __restrict__ enc,
            const float* __restrict__ emb,
            const float* __restrict__ comb_w,
            const float* __restrict__ comb_b,
            float* __restrict__ out)
{
    const int tid = threadIdx.x, bid = blockIdx.x;
    const int wid = tid >> 5, lane = tid & 31;
    __shared__ __align__(16) float s_in[H2];
    __shared__ __align__(16) float s_aw[SEQ];
    __shared__ __align__(16) float s_part[NWARP][H];
    __shared__ float s_red[NWARP];
    __shared__ float s_bc[2];

    // ---- x-independent prologue: comb weights + comb bias + emb row --------
    const int j = bid * NWARP + wid;
    const float4* w4 = (const float4*)(comb_w + (size_t)j * H2);
    float4 A[4];
    #pragma unroll
    for (int t = 0; t < 4; t++) A[t] = __ldg(w4 + lane + 32 * t);
    float cbias = __ldg(comb_b + j);
    {
        const int tok = token[0];
        const float* erow = emb + (size_t)tok * H;
        if (tid < H) s_in[tid] = __ldg(erow + tid);
    }
    pdl_wait();

    // ---- softmax over logits (redundant per block) ----
    float v = (tid < SEQ) ? g_attn_logits[tid] : -1e30f;
    float wm = v;
    #pragma unroll
    for (int o = 16; o; o >>= 1) wm = fmaxf(wm, __shfl_xor_sync(0xffffffffu, wm, o));
    if (lane == 0) s_red[wid] = wm;
    __syncthreads();
    if (tid == 0) {
        float m = s_red[0];
        #pragma unroll
        for (int w = 1; w < NWARP; w++) m = fmaxf(m, s_red[w]);
        s_bc[0] = m;
    }
    __syncthreads();
    float ex = (tid < SEQ) ? expf(v - s_bc[0]) : 0.f;
    float ws = ex;
    #pragma unroll
    for (int o = 16; o; o >>= 1) ws += __shfl_xor_sync(0xffffffffu, ws, o);
    if (lane == 0) s_red[wid] = ws;
    __syncthreads();
    if (tid == 0) {
        float s = 0.f;
        #pragma unroll
        for (int w = 0; w < NWARP; w++) s += s_red[w];
        s_bc[1] = s;
    }
    __syncthreads();
    float aw = ex / s_bc[1];
    if (tid < SEQ) s_aw[tid] = aw;
    __syncthreads();

    // ---- attn_applied: warp w covers seq [16w,16w+16), lanes cover columns
    {
        float acc[8];
        #pragma unroll
        for (int c8 = 0; c8 < 8; c8++) acc[c8] = 0.f;
        int i0 = wid * 16;
        #pragma unroll 4
        for (int ii = 0; ii < 16; ii++) {
            float a = s_aw[i0 + ii];
            const float* er = enc + (size_t)(i0 + ii) * H;
            #pragma unroll
            for (int c8 = 0; c8 < 8; c8++)
                acc[c8] = fmaf(a, __ldg(er + c8 * 32 + lane), acc[c8]);
        }
        #pragma unroll
        for (int c8 = 0; c8 < 8; c8++) s_part[wid][c8 * 32 + lane] = acc[c8];
    }
    __syncthreads();
    if (tid < H) {
        float ap = 0.f;
        #pragma unroll
        for (int w = 0; w < NWARP; w++) ap += s_part[w][tid];
        s_in[H + tid] = ap;
    }
    __syncthreads();

    // ---- comb: warp per row j (16 blocks x 16 warps = 256) ----
    {
        const float4* in4 = (const float4*)s_in;
        float4 xv[4];
        #pragma unroll
        for (int t = 0; t < 4; t++) xv[t] = in4[lane + 32 * t];
        float d = 0.f;
        #pragma unroll
        for (int t = 0; t < 4; t++) d += dot4f(A[t], xv[t]);
        d = wredsum(d);
        if (lane == 0) g_xbuf[0][j] = fmaxf(d + cbias, 0.f);
    }
    __threadfence();
    pdl_trigger();
    // attn_weights output (not needed by dependents)
    if (bid == 0 && tid < SEQ) out[VOC + NL * H + tid] = s_aw[tid];
}

// ====================== K3: one GRU layer (grid 16) =========================
__global__ void __launch_bounds__(TPB, 1)
k_gru(const float* __restrict__ hidden,
      const float* __restrict__ gru_wih,
      const float* __restrict__ gru_bih,
      float* __restrict__ out, int l)
{
    const int tid = threadIdx.x, bid = blockIdx.x;
    const int wid = tid >> 5, lane = tid & 31;
    __shared__ __align__(16) float s_x[H];

    // ---- x-independent prologue: weights + epilogue scalars ---------------
    const int j = bid * NWARP + wid;
    const float* wih = gru_wih + (size_t)l * 3 * H * H;
    const float4* wr = (const float4*)(wih + (size_t)j * H);
    const float4* wz = (const float4*)(wih + (size_t)(H + j) * H);
    const float4* wn = (const float4*)(wih + (size_t)(2 * H + j) * H);
    float4 W0 = __ldg(wr + lane), W1 = __ldg(wr + lane + 32);
    float4 W2 = __ldg(wz + lane), W3 = __ldg(wz + lane + 32);
    float4 W4 = __ldg(wn + lane), W5 = __ldg(wn + lane + 32);
    float p_ghr = g_gh[(l * 3 + 0) * H + j];
    float p_ghz = g_gh[(l * 3 + 1) * H + j];
    float p_ghn = g_gh[(l * 3 + 2) * H + j];
    float p_br  = __ldg(gru_bih + (l * 3 + 0) * H + j);
    float p_bz  = __ldg(gru_bih + (l * 3 + 1) * H + j);
    float p_bn  = __ldg(gru_bih + (l * 3 + 2) * H + j);
    float p_h   = __ldg(hidden + l * H + j);
    pdl_wait();

    if (tid < H) s_x[tid] = g_xbuf[l & 1][tid];
    __syncthreads();
    const float4* x4 = (const float4*)s_x;
    float4 xa = x4[lane], xb = x4[lane + 32];
    float dr = dot4f(W0, xa) + dot4f(W1, xb);
    float dz = dot4f(W2, xa) + dot4f(W3, xb);
    float dn = dot4f(W4, xa) + dot4f(W5, xb);
    float v = red4(dr, dz, dn, 0.f, lane);
    float rs = __shfl_sync(0xffffffffu, v, 0);
    float zs = __shfl_sync(0xffffffffu, v, 8);
    float ns = __shfl_sync(0xffffffffu, v, 16);
    float hnew = 0.f;
    if (lane == 0) {
        float r = 1.f / (1.f + expf(-((rs + p_br) + p_ghr)));
        float z = 1.f / (1.f + expf(-((zs + p_bz) + p_ghz)));
        float n = tanhf((ns + p_bn) + r * p_ghn);
        hnew = (1.f - z) * n + z * p_h;
        g_xbuf[(l + 1) & 1][j] = hnew;
    }
    __threadfence();
    pdl_trigger();
    if (lane == 0) out[VOC + l * H + j] = hnew;   // hidden_new output
}

// ====================== K4: GEMV + per-block (m,s) (grid 148) ===============
__global__ void __launch_bounds__(TPB, 1)
k_gemv(const float* __restrict__ out_w,
       const float* __restrict__ out_b,
       float* __restrict__ out)
{
    const int tid = threadIdx.x, bid = blockIdx.x;
    const int wid = tid >> 5, lane = tid & 31;
    __shared__ __align__(16) float s_x[H];
    __shared__ float s_ms[2 * NWARP];

    const int gwid = bid * NWARP + wid;
    const int rown = lane >> 2;
    const bool own = (lane & 3) == 0;

    // ---- x-independent prologue: preload iteration-0 tiles + bias ----------
    float4 A0[16];
    {
        int r0 = gwid * 8;
        #pragma unroll
        for (int i = 0; i < 8; i++) {
            int row = r0 + i; if (row > VOC - 1) row = VOC - 1;
            const float4* wr = (const float4*)(out_w + (size_t)row * H);
            A0[2 * i]     = __ldg(wr + lane);
            A0[2 * i + 1] = __ldg(wr + lane + 32);
        }
    }
    float bias0 = 0.f;
    {
        int myrow = gwid * 8 + rown;
        if (own && myrow < VOC) bias0 = __ldg(out_b + myrow);
    }
    pdl_wait();

    if (tid < H) s_x[tid] = g_xbuf[0][tid];   // NL even -> buf 0
    __syncthreads();
    const float4* x4 = (const float4*)s_x;
    float4 xa = x4[lane], xb = x4[lane + 32];
    float mM = -1e30f, sS = 0.f;

    // ---- iteration 0 from preloaded tiles ----------------------------------
    {
        int r0 = gwid * 8;
        int myrow = r0 + rown;
        float d[8];
        #pragma unroll
        for (int i = 0; i < 8; i++)
            d[i] = dot4f(A0[2 * i], xa) + dot4f(A0[2 * i + 1], xb);
        float v = red8(d, lane);
        if (own && myrow < VOC) {
            v += bias0;
            out[myrow] = v;
            float m2 = fmaxf(mM, v);
            sS = sS * expf(mM - m2) + expf(v - m2);
            mM = m2;
        }
    }
    // ---- iterations 1..2 ----------------------------------------------------
    #pragma unroll 1
    for (int it = 1; it < GEMV_ITERS; it++) {
        int r0 = (it * GEMV_TOTW + gwid) * 8;
        int myrow = r0 + rown;
        float bias = (own && myrow < VOC) ? __ldg(out_b + myrow) : 0.f;
        float d[8];
        #pragma unroll
        for (int i = 0; i < 8; i++) {
            int row = r0 + i;
            float s = 0.f;
            if (row < VOC) {
                const float4* wr = (const float4*)(out_w + (size_t)row * H);
                float4 a0 = __ldg(wr + lane), a1 = __ldg(wr + lane + 32);
                s = dot4f(a0, xa) + dot4f(a1, xb);
            }
            d[i] = s;
        }
        float v = red8(d, lane);
        if (own && myrow < VOC) {
            v += bias;
            out[myrow] = v;
            float m2 = fmaxf(mM, v);
            sS = sS * expf(mM - m2) + expf(v - m2);
            mM = m2;
        }
    }
    #pragma unroll
    for (int o = 16; o; o >>= 1) {
        float om = __shfl_xor_sync(0xffffffffu, mM, o);
        float os = __shfl_xor_sync(0xffffffffu, sS, o);
        float m2 = fmaxf(mM, om);
        sS = sS * expf(mM - m2) + os * expf(om - m2);
        mM = m2;
    }
    if (lane == 0) { s_ms[wid] = mM; s_ms[NWARP + wid] = sS; }
    __syncthreads();
    if (tid == 0) {
        float M = s_ms[0], S = s_ms[NWARP];
        #pragma unroll
        for (int w = 1; w < NWARP; w++) {
            float m2 = fmaxf(M, s_ms[w]);
            S = S * expf(M - m2) + s_ms[NWARP + w] * expf(s_ms[w] - m2);
            M = m2;
        }
        g_red[bid] = make_float2(M, S);
    }
    __threadfence();
    pdl_trigger();
}

// ====================== K5: finalize lse + subtract (grid 148) ==============
__global__ void __launch_bounds__(TPB, 1)
k_final(float* __restrict__ out)
{
    const int tid = threadIdx.x, bid = blockIdx.x;
    const int wid = tid >> 5, lane = tid & 31;
    __shared__ float s_lse;

    pdl_wait();
    if (wid == 0) {
        float M = -1e30f, S = 0.f;
        for (int k = lane; k < GEMV_GRID; k += 32) {
            float2 p = g_red[k];
            float m2 = fmaxf(M, p.x);
            S = S * expf(M - m2) + p.y * expf(p.x - m2);
            M = m2;
        }
        #pragma unroll
        for (int o = 16; o; o >>= 1) {
            float om = __shfl_xor_sync(0xffffffffu, M, o);
            float os = __shfl_xor_sync(0xffffffffu, S, o);
            float m2 = fmaxf(M, om);
            S = S * expf(M - m2) + os * expf(om - m2);
            M = m2;
        }
        if (lane == 0) s_lse = M + logf(S);
    }
    __syncthreads();
    float lse = s_lse;
    int i = bid * TPB + tid;          // 148*512 = 75776 >= VOC, one pass
    if (i < VOC) out[i] -= lse;
}

// ---------------- host: PDL launch helper -----------------------------------
static void launch_pdl(const void* func, dim3 grid, dim3 block, void** args) {
    cudaLaunchConfig_t cfg = {};
    cfg.gridDim = grid;
    cfg.blockDim = block;
    cfg.dynamicSmemBytes = 0;
    cfg.stream = 0;
    cudaLaunchAttribute attr[1];
    attr[0].id = cudaLaunchAttributeProgrammaticStreamSerialization;
    attr[0].val.programmaticStreamSerializationAllowed = 1;
    cfg.attrs = attr;
    cfg.numAttrs = 1;
    cudaLaunchKernelExC(&cfg, func, args);
}

extern "C" void kernel_launch(void* const* d_in, const int* in_sizes, int n_in,
                              void* d_out, int out_size) {
    const int*   token   = (const int*)d_in[0];
    const float* hidden  = (const float*)d_in[1];
    const float* enc     = (const float*)d_in[2];
    const float* emb     = (const float*)d_in[3];
    const float* attn_w  = (const float*)d_in[4];
    const float* attn_b  = (const float*)d_in[5];
    const float* comb_w  = (const float*)d_in[6];
    const float* comb_b  = (const float*)d_in[7];
    const float* gru_wih = (const float*)d_in[8];
    const float* gru_whh = (const float*)d_in[9];
    const float* gru_bih = (const float*)d_in[10];
    const float* gru_bhh = (const float*)d_in[11];
    const float* out_w   = (const float*)d_in[12];
    const float* out_b   = (const float*)d_in[13];
    float* out = (float*)d_out;

    // node 1: plain launch
    k_logits_gh<<<80, TPB>>>(token, hidden, emb, attn_w, attn_b, gru_whh, gru_bhh);

    // node 2: PDL
    {
        void* a[] = {(void*)&token, (void*)&enc, (void*)&emb, (void*)&comb_w,
                     (void*)&comb_b, (void*)&out};
        launch_pdl((const void*)k_attn_comb, dim3(16), dim3(TPB), a);
    }
    // nodes 3-6: GRU layers, PDL
    static int ls[NL] = {0, 1, 2, 3};
    for (int l = 0; l < NL; l++) {
        void* a[] = {(void*)&hidden, (void*)&gru_wih, (void*)&gru_bih,
                     (void*)&out, (void*)&ls[l]};
        launch_pdl((const void*)k_gru, dim3(16), dim3(TPB), a);
    }
    // node 7: GEMV, PDL
    {
        void* a[] = {(void*)&out_w, (void*)&out_b, (void*)&out};
        launch_pdl((const void*)k_gemv, dim3(GEMV_GRID), dim3(TPB), a);
    }
    // node 8: finalize, PDL
    {
        void* a[] = {(void*)&out};
        launch_pdl((const void*)k_final, dim3(GEMV_GRID), dim3(TPB), a);
    }
}